// round 14
// baseline (speedup 1.0000x reference)
#include <cuda_runtime.h>
#include <cuda_fp16.h>
#include <stdint.h>
#include <math.h>

#define BB     4
#define LL     8192
#define DD     1024
#define HH     16
#define DH     64
#define MLROWS (BB * LL)          // 32768
#define NQKV   (3 * DD)           // 3072
#define EPSV   1e-6f
#define SPLITS 32
#define LCHUNK (LL / SPLITS)      // 256

// GEMM tiling: CTA 128x256, 16 warps (4x4), warp tile 32x64, K-chunk 64
#define KC 64
#define NCH (DD / KC)              // 16
#define GTHREADS 512
#define STAGE_BYTES 49152          // A 16K, B 32K
#define GEMM_SMEM   (2 * STAGE_BYTES)

// ---------------- scratch (static device globals; no allocation) ----------
__device__ __half g_X16[(size_t)MLROWS * DD];
__device__ __half g_Q16[(size_t)MLROWS * DD];   // phi(xWq)
__device__ __half g_K16[(size_t)MLROWS * DD];   // phi(xWk)
__device__ __half g_V16[(size_t)MLROWS * DD];   // xWv
__device__ __half g_att16[(size_t)MLROWS * DD];
__device__ float g_KvPart[BB * HH * SPLITS * DH * DH];
__device__ float g_K1Part[BB * HH * SPLITS * DH];
__device__ __half g_Kv16[BB * HH * DH * DH];
__device__ float g_K1[BB * HH * DH];
__device__ __half g_Wt[4][DD * DD];             // [N,K] fp16 (Wq|Wk|Wv|Wo)

// =========================== helpers ==================================
__device__ __forceinline__ uint32_t smem_u32(const void* p) {
    return (uint32_t)__cvta_generic_to_shared(p);
}

#define LDSM_X4(r0, r1, r2, r3, addr) \
    asm volatile("ldmatrix.sync.aligned.m8n8.x4.shared.b16 {%0,%1,%2,%3}, [%4];" \
                 : "=r"(r0), "=r"(r1), "=r"(r2), "=r"(r3) : "r"(addr))

#define LDSM_X4_T(r0, r1, r2, r3, addr) \
    asm volatile("ldmatrix.sync.aligned.m8n8.x4.trans.shared.b16 {%0,%1,%2,%3}, [%4];" \
                 : "=r"(r0), "=r"(r1), "=r"(r2), "=r"(r3) : "r"(addr))

#define MMA16816H(d, a, b0, b1) \
    asm volatile("mma.sync.aligned.m16n8k16.row.col.f32.f16.f16.f32 " \
                 "{%0,%1,%2,%3}, {%4,%5,%6,%7}, {%8,%9}, {%0,%1,%2,%3};" \
                 : "+f"((d)[0]), "+f"((d)[1]), "+f"((d)[2]), "+f"((d)[3]) \
                 : "r"((a)[0]), "r"((a)[1]), "r"((a)[2]), "r"((a)[3]), \
                   "r"(b0), "r"(b1))

__device__ __forceinline__ void cp16(uint32_t dst, const void* src) {
    asm volatile("cp.async.cg.shared.global [%0], [%1], 16;"
                 :: "r"(dst), "l"(src));
}
#define CP_COMMIT() asm volatile("cp.async.commit_group;" ::: "memory")
#define CP_WAIT(n)  asm volatile("cp.async.wait_group %0;" :: "n"(n) : "memory")

#define SWZ(off) ((off) ^ (((off) >> 3) & 0x70))

// ====== fused pre-pass: x fp32->fp16 AND four W[K,N]->Wt[N,K] fp16 ========
#define XBLOCKS (MLROWS * DD / 1024)            // 32768
__global__ __launch_bounds__(256)
void prepass_k(const float* __restrict__ X, __half* __restrict__ H,
               const float* __restrict__ W0, const float* __restrict__ W1,
               const float* __restrict__ W2, const float* __restrict__ W3,
               __half* __restrict__ T) {
    if (blockIdx.x < XBLOCKS) {
        size_t i = ((size_t)blockIdx.x * 256 + threadIdx.x) * 4;
        float4 v = *(const float4*)(X + i);
        __half2 a = __floats2half2_rn(v.x, v.y);
        __half2 b = __floats2half2_rn(v.z, v.w);
        *(uint2*)(H + i) = make_uint2(*(uint32_t*)&a, *(uint32_t*)&b);
        return;
    }
    const int idx = blockIdx.x - XBLOCKS;       // 0..4095
    const int z   = idx >> 10;                  // 0..3
    const int rem = idx & 1023;
    const float* W = (z == 0) ? W0 : (z == 1) ? W1 : (z == 2) ? W2 : W3;
    __half* Tz = T + (size_t)z * DD * DD;
    __shared__ float t[32][33];
    const int nb = (rem & 31) * 32;
    const int kb = (rem >> 5) * 32;
    const int tx = threadIdx.x & 31;
    const int ty = threadIdx.x >> 5;
    for (int i = ty; i < 32; i += 8)
        t[i][tx] = W[(size_t)(kb + i) * DD + nb + tx];
    __syncthreads();
    for (int i = ty; i < 32; i += 8) {
        size_t o = (size_t)(nb + i) * DD + kb + tx;
        Tz[o] = __float2half_rn(t[tx][i]);
    }
}

// ========== mma.sync fp16 GEMM (1-term, 2-stage cp.async) =================
__device__ __forceinline__ void cpa_chunk(
    uint32_t sb,
    const __half* __restrict__ A, const __half* __restrict__ B,
    int bm, int bn, int k0, int tid) {
#pragma unroll
    for (int t = 0; t < 2; ++t) {
        int idx = tid + t * GTHREADS;
        int row = idx >> 3;
        int cb  = (idx & 7) << 4;
        uint32_t off = (uint32_t)(row * 128 + cb);
        cp16(sb + SWZ(off), (const char*)(A + (size_t)(bm + row) * DD + k0) + cb);
    }
#pragma unroll
    for (int t = 0; t < 4; ++t) {
        int idx = tid + t * GTHREADS;
        int row = idx >> 3;
        int cb  = (idx & 7) << 4;
        uint32_t off = (uint32_t)(row * 128 + cb);
        cp16(sb + 16384 + SWZ(off), (const char*)(B + (size_t)(bn + row) * DD + k0) + cb);
    }
}

__device__ __forceinline__ void compute_chunk(
    uint32_t sb, int wm, int wn, int lane, float acc[2][8][4]) {
    const uint32_t sA = sb, sB = sb + 16384;
    const int i   = lane & 7;
    const int sub = lane >> 3;
#pragma unroll
    for (int ks = 0; ks < 4; ++ks) {
        uint32_t a[2][4], b[8][2];
#pragma unroll
        for (int mt = 0; mt < 2; ++mt) {
            int row = wm * 32 + mt * 16 + i + ((sub & 1) << 3);
            int kk  = ks * 16 + ((sub & 2) << 2);
            uint32_t off = (uint32_t)(row * 128 + kk * 2);
            LDSM_X4(a[mt][0], a[mt][1], a[mt][2], a[mt][3], sA + SWZ(off));
        }
#pragma unroll
        for (int np = 0; np < 4; ++np) {
            int row = wn * 64 + np * 16 + i + ((sub & 2) << 2);
            int kk  = ks * 16 + ((sub & 1) << 3);
            uint32_t off = (uint32_t)(row * 128 + kk * 2);
            uint32_t r0, r1, r2, r3;
            LDSM_X4(r0, r1, r2, r3, sB + SWZ(off));
            b[2 * np][0] = r0; b[2 * np][1] = r1;
            b[2 * np + 1][0] = r2; b[2 * np + 1][1] = r3;
        }
#pragma unroll
        for (int mt = 0; mt < 2; ++mt)
#pragma unroll
            for (int nt = 0; nt < 8; ++nt)
                MMA16816H(acc[mt][nt], a[mt], b[nt][0], b[nt][1]);
    }
}

template <int QKVMODE>
__global__ __launch_bounds__(GTHREADS, 1)
void mma_gemm_k(const __half* __restrict__ A,
                const __half* __restrict__ B,
                float* __restrict__ C,
                __half* __restrict__ Q16, __half* __restrict__ K16,
                __half* __restrict__ V16,
                int Ncols, int phiLimit) {
    extern __shared__ char sm[];
    const uint32_t s0 = smem_u32(sm);

    const int tid  = threadIdx.x;
    const int wid  = tid >> 5;
    const int lane = tid & 31;
    const int wm   = wid >> 2;
    const int wn   = wid & 3;
    const int bm   = blockIdx.y * 128;
    const int bn   = blockIdx.x * 256;
    const bool phi = bn < phiLimit;

    float acc[2][8][4];
#pragma unroll
    for (int mt = 0; mt < 2; ++mt)
#pragma unroll
        for (int nt = 0; nt < 8; ++nt)
#pragma unroll
            for (int j = 0; j < 4; ++j) acc[mt][nt][j] = 0.f;

    cpa_chunk(s0, A, B, bm, bn, 0, tid);
    CP_COMMIT();

    for (int ch = 0; ch < NCH; ++ch) {
        if (ch + 1 < NCH) {
            cpa_chunk(s0 + (uint32_t)((ch + 1) & 1) * STAGE_BYTES,
                      A, B, bm, bn, (ch + 1) * KC, tid);
            CP_COMMIT();
            CP_WAIT(1);
        } else {
            CP_WAIT(0);
        }
        __syncthreads();
        compute_chunk(s0 + (uint32_t)(ch & 1) * STAGE_BYTES, wm, wn, lane, acc);
        __syncthreads();
    }

#pragma unroll
    for (int mt = 0; mt < 2; ++mt)
#pragma unroll
        for (int nt = 0; nt < 8; ++nt) {
            int row = bm + wm * 32 + mt * 16 + (lane >> 2);
            int col = bn + wn * 64 + nt * 8 + (lane & 3) * 2;
            float2 v0 = make_float2(acc[mt][nt][0], acc[mt][nt][1]);
            float2 v1 = make_float2(acc[mt][nt][2], acc[mt][nt][3]);
            if (phi) {
                v0.x = (v0.x > 0.f) ? (v0.x + 1.f) : expf(v0.x);
                v0.y = (v0.y > 0.f) ? (v0.y + 1.f) : expf(v0.y);
                v1.x = (v1.x > 0.f) ? (v1.x + 1.f) : expf(v1.x);
                v1.y = (v1.y > 0.f) ? (v1.y + 1.f) : expf(v1.y);
            }
            if (QKVMODE == 0) {
                *(float2*)(C + (size_t)row * Ncols + col)       = v0;
                *(float2*)(C + (size_t)(row + 8) * Ncols + col) = v1;
            } else {
                const int blk  = col >> 10;
                const int lcol = col & 1023;
                __half* dst = (blk == 0) ? Q16 : (blk == 1) ? K16 : V16;
                size_t o0 = (size_t)row * DD + lcol;
                size_t o1 = (size_t)(row + 8) * DD + lcol;
                *(__half2*)(dst + o0) = __floats2half2_rn(v0.x, v0.y);
                *(__half2*)(dst + o1) = __floats2half2_rn(v1.x, v1.y);
            }
        }
}

// ---- kv_part: Kv += Kf^T V (HMMA), register-prefetch over l-chunks -------
__global__ __launch_bounds__(256)
void kv_part_k() {
    const int bh    = blockIdx.x;
    const int split = blockIdx.y;
    const int b = bh >> 4, h = bh & 15;

    __shared__ __half Kt[64 * 64];
    __shared__ __half Vt[64 * 64];
    __shared__ float k1s[DH];

    const int tid  = threadIdx.x;
    const int wid  = tid >> 5;
    const int lane = tid & 31;
    const int wm   = wid >> 1;
    const int wn   = wid & 1;
    const int i    = lane & 7;
    const int sub  = lane >> 3;
    const uint32_t sK = smem_u32(Kt);
    const uint32_t sV = smem_u32(Vt);

    if (tid < DH) k1s[tid] = 0.f;

    float acc[4][4];
#pragma unroll
    for (int nt = 0; nt < 4; ++nt)
#pragma unroll
        for (int j = 0; j < 4; ++j) acc[nt][j] = 0.f;
    float k1loc[4] = {0.f, 0.f, 0.f, 0.f};

    const int c4 = (tid & 15) << 2;
    const int lrow = tid >> 4;           // 0..15
    const size_t gbase = ((size_t)b * LL) * DD + (size_t)h * DH;
    const int l0 = split * LCHUNK;

    uint2 kr[4], vr[4];
#pragma unroll
    for (int t = 0; t < 4; ++t) {
        size_t g = gbase + (size_t)(l0 + lrow + t * 16) * DD + c4;
        kr[t] = *(const uint2*)(g_K16 + g);
        vr[t] = *(const uint2*)(g_V16 + g);
    }

    for (int ch = 0; ch < LCHUNK / 64; ++ch) {
        __syncthreads();
#pragma unroll
        for (int t = 0; t < 4; ++t) {
            int l = lrow + t * 16;
            uint32_t sw = SWZ((uint32_t)(l * 128 + c4 * 2));
            *(uint2*)((char*)Kt + sw) = kr[t];
            *(uint2*)((char*)Vt + sw) = vr[t];
            float2 f0 = __half22float2(*(__half2*)&kr[t].x);
            float2 f1 = __half22float2(*(__half2*)&kr[t].y);
            k1loc[0] += f0.x; k1loc[1] += f0.y;
            k1loc[2] += f1.x; k1loc[3] += f1.y;
        }
        __syncthreads();

        if (ch + 1 < LCHUNK / 64) {
#pragma unroll
            for (int t = 0; t < 4; ++t) {
                size_t g = gbase + (size_t)(l0 + (ch + 1) * 64 + lrow + t * 16) * DD + c4;
                kr[t] = *(const uint2*)(g_K16 + g);
                vr[t] = *(const uint2*)(g_V16 + g);
            }
        }

#pragma unroll
        for (int ks = 0; ks < 4; ++ks) {
            uint32_t a[4];
            {
                int row = ks * 16 + ((sub & 2) << 2) + i;
                int col = wm * 16 + ((sub & 1) << 3);
                uint32_t off = (uint32_t)(row * 128 + col * 2);
                LDSM_X4_T(a[0], a[1], a[2], a[3], sK + SWZ(off));
            }
            uint32_t bf[4][2];
#pragma unroll
            for (int np = 0; np < 2; ++np) {
                int row = ks * 16 + ((sub & 1) << 3) + i;
                int col = wn * 32 + np * 16 + ((sub & 2) << 2);
                uint32_t off = (uint32_t)(row * 128 + col * 2);
                uint32_t r0, r1, r2, r3;
                LDSM_X4_T(r0, r1, r2, r3, sV + SWZ(off));
                bf[2 * np][0] = r0; bf[2 * np][1] = r1;
                bf[2 * np + 1][0] = r2; bf[2 * np + 1][1] = r3;
            }
#pragma unroll
            for (int nt = 0; nt < 4; ++nt)
                MMA16816H(acc[nt], a, bf[nt][0], bf[nt][1]);
        }
    }

#pragma unroll
    for (int j = 0; j < 4; ++j) atomicAdd(&k1s[c4 + j], k1loc[j]);
    __syncthreads();

    float* kp = g_KvPart + ((size_t)bh * SPLITS + split) * (DH * DH);
    const int r0 = wm * 16 + (lane >> 2);
#pragma unroll
    for (int nt = 0; nt < 4; ++nt) {
        int cc = wn * 32 + nt * 8 + (lane & 3) * 2;
        *(float2*)(kp + r0 * DH + cc)       = make_float2(acc[nt][0], acc[nt][1]);
        *(float2*)(kp + (r0 + 8) * DH + cc) = make_float2(acc[nt][2], acc[nt][3]);
    }
    if (tid < DH)
        g_K1Part[((size_t)bh * SPLITS + split) * DH + tid] = k1s[tid];
}

// ---------------- reduce partials: Kv -> fp16, K1 -> fp32 -----------------
__global__ __launch_bounds__(256)
void kv_reduce_k() {
    const int bh  = blockIdx.x;
    const int tid = threadIdx.x;
    for (int idx = tid; idx < DH * DH; idx += 256) {
        float s = 0.f;
#pragma unroll
        for (int sp = 0; sp < SPLITS; ++sp)
            s += g_KvPart[((size_t)bh * SPLITS + sp) * (DH * DH) + idx];
        g_Kv16[(size_t)bh * (DH * DH) + idx] = __float2half_rn(s);
    }
    if (tid < DH) {
        float s = 0.f;
#pragma unroll
        for (int sp = 0; sp < SPLITS; ++sp)
            s += g_K1Part[((size_t)bh * SPLITS + sp) * DH + tid];
        g_K1[bh * DH + tid] = s;
    }
}

// -------- numden: att = (Qf @ Kv16) / (Qf @ K1 + eps) via HMMA ------------
__global__ __launch_bounds__(256)
void numden_k() {
    const int bh = blockIdx.x;
    const int lt = blockIdx.y;
    const int b = bh >> 4, h = bh & 15;

    __shared__ __half Qs[64 * 64];
    __shared__ __half Kvs[64 * 64];
    __shared__ float K1s[DH];

    const int tid  = threadIdx.x;
    const int wid  = tid >> 5;
    const int lane = tid & 31;
    const int wm   = wid >> 1;
    const int wn   = wid & 1;
    const int i    = lane & 7;
    const int sub  = lane >> 3;
    const uint32_t sQ  = smem_u32(Qs);
    const uint32_t sKv = smem_u32(Kvs);

    const size_t base = ((size_t)b * LL + (size_t)lt * 64) * DD + (size_t)h * DH;
    const int c4 = (tid & 15) << 2;

#pragma unroll
    for (int t = 0; t < 4; ++t) {
        int r = (tid >> 4) + t * 16;
        uint32_t off = (uint32_t)(r * 128 + c4 * 2);
        uint32_t sw  = SWZ(off);
        *(uint2*)((char*)Qs + sw) =
            *(const uint2*)(g_Q16 + base + (size_t)r * DD + c4);
        *(uint2*)((char*)Kvs + sw) =
            *(const uint2*)(g_Kv16 + (size_t)bh * DH * DH + r * DH + c4);
    }
    if (tid < DH) K1s[tid] = g_K1[bh * DH + tid];
    __syncthreads();

    float acc[4][4];
#pragma unroll
    for (int nt = 0; nt < 4; ++nt)
#pragma unroll
        for (int j = 0; j < 4; ++j) acc[nt][j] = 0.f;
    float den_lo = 0.f, den_hi = 0.f;
    const int q2 = (lane & 3) * 2;

#pragma unroll
    for (int ks = 0; ks < 4; ++ks) {
        uint32_t a[4];
        {
            int row = wm * 16 + i + ((sub & 1) << 3);
            int kk  = ks * 16 + ((sub & 2) << 2);
            uint32_t off = (uint32_t)(row * 128 + kk * 2);
            LDSM_X4(a[0], a[1], a[2], a[3], sQ + SWZ(off));
        }
        float k00 = K1s[ks * 16 + q2],     k01 = K1s[ks * 16 + q2 + 1];
        float k10 = K1s[ks * 16 + 8 + q2], k11 = K1s[ks * 16 + 8 + q2 + 1];
        float2 f;
        f = __half22float2(*(__half2*)&a[0]); den_lo += f.x * k00 + f.y * k01;
        f = __half22float2(*(__half2*)&a[1]); den_hi += f.x * k00 + f.y * k01;
        f = __half22float2(*(__half2*)&a[2]); den_lo += f.x * k10 + f.y * k11;
        f = __half22float2(*(__half2*)&a[3]); den_hi += f.x * k10 + f.y * k11;

        uint32_t bf[4][2];
#pragma unroll
        for (int np = 0; np < 2; ++np) {
            int row = ks * 16 + ((sub & 1) << 3) + i;
            int col = wn * 32 + np * 16 + ((sub & 2) << 2);
            uint32_t off = (uint32_t)(row * 128 + col * 2);
            uint32_t r0, r1, r2, r3;
            LDSM_X4_T(r0, r1, r2, r3, sKv + SWZ(off));
            bf[2 * np][0] = r0; bf[2 * np][1] = r1;
            bf[2 * np + 1][0] = r2; bf[2 * np + 1][1] = r3;
        }
#pragma unroll
        for (int nt = 0; nt < 4; ++nt)
            MMA16816H(acc[nt], a, bf[nt][0], bf[nt][1]);
    }

#pragma unroll
    for (int s = 1; s < 4; s <<= 1) {
        den_lo += __shfl_xor_sync(0xffffffffu, den_lo, s);
        den_hi += __shfl_xor_sync(0xffffffffu, den_hi, s);
    }
    const float inv_lo = 1.f / (den_lo + EPSV);
    const float inv_hi = 1.f / (den_hi + EPSV);

    const int r0 = wm * 16 + (lane >> 2);
#pragma unroll
    for (int nt = 0; nt < 4; ++nt) {
        int cc = wn * 32 + nt * 8 + (lane & 3) * 2;
        __half2 o0 = __floats2half2_rn(acc[nt][0] * inv_lo, acc[nt][1] * inv_lo);
        __half2 o1 = __floats2half2_rn(acc[nt][2] * inv_hi, acc[nt][3] * inv_hi);
        *(uint32_t*)(g_att16 + base + (size_t)r0 * DD + cc)       = *(uint32_t*)&o0;
        *(uint32_t*)(g_att16 + base + (size_t)(r0 + 8) * DD + cc) = *(uint32_t*)&o1;
    }
}

// --------------------------- host launch --------------------------------
extern "C" void kernel_launch(void* const* d_in, const int* in_sizes, int n_in,
                              void* d_out, int out_size) {
    const float* x  = (const float*)d_in[0];
    const float* Wq = (const float*)d_in[1];
    const float* Wk = (const float*)d_in[2];
    const float* Wv = (const float*)d_in[3];
    const float* Wo = (const float*)d_in[4];
    float* out = (float*)d_out;

    __half *x16, *q16, *k16, *v16, *att16, *wt;
    cudaGetSymbolAddress((void**)&x16,   g_X16);
    cudaGetSymbolAddress((void**)&q16,   g_Q16);
    cudaGetSymbolAddress((void**)&k16,   g_K16);
    cudaGetSymbolAddress((void**)&v16,   g_V16);
    cudaGetSymbolAddress((void**)&att16, g_att16);
    cudaGetSymbolAddress((void**)&wt,    g_Wt);

    cudaFuncSetAttribute(mma_gemm_k<0>,
                         cudaFuncAttributeMaxDynamicSharedMemorySize, GEMM_SMEM);
    cudaFuncSetAttribute(mma_gemm_k<1>,
                         cudaFuncAttributeMaxDynamicSharedMemorySize, GEMM_SMEM);

    // fused pre-pass: x conversion + 4 weight transposes in one launch
    prepass_k<<<XBLOCKS + 4096, 256>>>(x, x16, Wq, Wk, Wv, Wo, wt);

    // fused QKV GEMM: N = 3072, phi on cols < 2048; writes Q16/K16/V16
    dim3 gqkv(NQKV / 256, MLROWS / 128);      // (12, 256)
    mma_gemm_k<1><<<gqkv, GTHREADS, GEMM_SMEM>>>(
        x16, wt, nullptr, q16, k16, v16, NQKV, 2 * DD);

    kv_part_k<<<dim3(BB * HH, SPLITS), 256>>>();
    kv_reduce_k<<<BB * HH, 256>>>();
    numden_k<<<dim3(BB * HH, LL / 64), 256>>>();

    // output GEMM: N = 1024, no phi, fp32 out
    dim3 gout(DD / 256, MLROWS / 128);        // (4, 256)
    mma_gemm_k<0><<<gout, GTHREADS, GEMM_SMEM>>>(
        att16, wt + 3 * (size_t)DD * DD, out,
        nullptr, nullptr, nullptr, DD, 0);
}

// round 15
// speedup vs baseline: 1.0284x; 1.0284x over previous
#include <cuda_runtime.h>
#include <cuda_fp16.h>
#include <stdint.h>
#include <math.h>

#define BB     4
#define LL     8192
#define DD     1024
#define HH     16
#define DH     64
#define MLROWS (BB * LL)          // 32768
#define NQKV   (3 * DD)           // 3072
#define EPSV   1e-6f
#define SPLITS 16
#define LCHUNK (LL / SPLITS)      // 512

// GEMM tiling: CTA 128x256, 16 warps (4x4), warp tile 32x64, K-chunk 64
#define KC 64
#define NCH (DD / KC)              // 16
#define GTHREADS 512
#define STAGE_BYTES 49152          // A 16K, B 32K
#define GEMM_SMEM   (2 * STAGE_BYTES)

// ---------------- scratch (static device globals; no allocation) ----------
__device__ __half g_X16[(size_t)MLROWS * DD];
__device__ __half g_Q16[(size_t)MLROWS * DD];   // phi(xWq)
__device__ __half g_K16[(size_t)MLROWS * DD];   // phi(xWk)
__device__ __half g_V16[(size_t)MLROWS * DD];   // xWv
__device__ __half g_att16[(size_t)MLROWS * DD];
__device__ float g_KvPart[BB * HH * SPLITS * DH * DH];
__device__ float g_K1Part[BB * HH * SPLITS * DH];
__device__ __half g_Kv16[BB * HH * DH * DH];
__device__ float g_K1[BB * HH * DH];
__device__ __half g_Wt[4][DD * DD];             // [N,K] fp16 (Wq|Wk|Wv|Wo)

// =========================== helpers ==================================
__device__ __forceinline__ uint32_t smem_u32(const void* p) {
    return (uint32_t)__cvta_generic_to_shared(p);
}

#define LDSM_X4(r0, r1, r2, r3, addr) \
    asm volatile("ldmatrix.sync.aligned.m8n8.x4.shared.b16 {%0,%1,%2,%3}, [%4];" \
                 : "=r"(r0), "=r"(r1), "=r"(r2), "=r"(r3) : "r"(addr))

#define LDSM_X4_T(r0, r1, r2, r3, addr) \
    asm volatile("ldmatrix.sync.aligned.m8n8.x4.trans.shared.b16 {%0,%1,%2,%3}, [%4];" \
                 : "=r"(r0), "=r"(r1), "=r"(r2), "=r"(r3) : "r"(addr))

#define MMA16816H(d, a, b0, b1) \
    asm volatile("mma.sync.aligned.m16n8k16.row.col.f32.f16.f16.f32 " \
                 "{%0,%1,%2,%3}, {%4,%5,%6,%7}, {%8,%9}, {%0,%1,%2,%3};" \
                 : "+f"((d)[0]), "+f"((d)[1]), "+f"((d)[2]), "+f"((d)[3]) \
                 : "r"((a)[0]), "r"((a)[1]), "r"((a)[2]), "r"((a)[3]), \
                   "r"(b0), "r"(b1))

__device__ __forceinline__ void cp16(uint32_t dst, const void* src) {
    asm volatile("cp.async.cg.shared.global [%0], [%1], 16;"
                 :: "r"(dst), "l"(src));
}
#define CP_COMMIT() asm volatile("cp.async.commit_group;" ::: "memory")
#define CP_WAIT(n)  asm volatile("cp.async.wait_group %0;" :: "n"(n) : "memory")

#define SWZ(off) ((off) ^ (((off) >> 3) & 0x70))

// ====== fused pre-pass: x fp32->fp16 AND four W[K,N]->Wt[N,K] fp16 ========
#define XBLOCKS (MLROWS * DD / 1024)            // 32768
__global__ __launch_bounds__(256)
void prepass_k(const float* __restrict__ X, __half* __restrict__ H,
               const float* __restrict__ W0, const float* __restrict__ W1,
               const float* __restrict__ W2, const float* __restrict__ W3,
               __half* __restrict__ T) {
    if (blockIdx.x < XBLOCKS) {
        size_t i = ((size_t)blockIdx.x * 256 + threadIdx.x) * 4;
        float4 v = *(const float4*)(X + i);
        __half2 a = __floats2half2_rn(v.x, v.y);
        __half2 b = __floats2half2_rn(v.z, v.w);
        *(uint2*)(H + i) = make_uint2(*(uint32_t*)&a, *(uint32_t*)&b);
        return;
    }
    const int idx = blockIdx.x - XBLOCKS;       // 0..4095
    const int z   = idx >> 10;                  // 0..3
    const int rem = idx & 1023;
    const float* W = (z == 0) ? W0 : (z == 1) ? W1 : (z == 2) ? W2 : W3;
    __half* Tz = T + (size_t)z * DD * DD;
    __shared__ float t[32][33];
    const int nb = (rem & 31) * 32;
    const int kb = (rem >> 5) * 32;
    const int tx = threadIdx.x & 31;
    const int ty = threadIdx.x >> 5;
    for (int i = ty; i < 32; i += 8)
        t[i][tx] = W[(size_t)(kb + i) * DD + nb + tx];
    __syncthreads();
    for (int i = ty; i < 32; i += 8) {
        size_t o = (size_t)(nb + i) * DD + kb + tx;
        Tz[o] = __float2half_rn(t[tx][i]);
    }
}

// ========== mma.sync fp16 GEMM (1-term, 2-stage cp.async) =================
__device__ __forceinline__ void cpa_chunk(
    uint32_t sb,
    const __half* __restrict__ A, const __half* __restrict__ B,
    int bm, int bn, int k0, int tid) {
#pragma unroll
    for (int t = 0; t < 2; ++t) {
        int idx = tid + t * GTHREADS;
        int row = idx >> 3;
        int cb  = (idx & 7) << 4;
        uint32_t off = (uint32_t)(row * 128 + cb);
        cp16(sb + SWZ(off), (const char*)(A + (size_t)(bm + row) * DD + k0) + cb);
    }
#pragma unroll
    for (int t = 0; t < 4; ++t) {
        int idx = tid + t * GTHREADS;
        int row = idx >> 3;
        int cb  = (idx & 7) << 4;
        uint32_t off = (uint32_t)(row * 128 + cb);
        cp16(sb + 16384 + SWZ(off), (const char*)(B + (size_t)(bn + row) * DD + k0) + cb);
    }
}

__device__ __forceinline__ void compute_chunk(
    uint32_t sb, int wm, int wn, int lane, float acc[2][8][4]) {
    const uint32_t sA = sb, sB = sb + 16384;
    const int i   = lane & 7;
    const int sub = lane >> 3;
#pragma unroll
    for (int ks = 0; ks < 4; ++ks) {
        uint32_t a[2][4], b[8][2];
#pragma unroll
        for (int mt = 0; mt < 2; ++mt) {
            int row = wm * 32 + mt * 16 + i + ((sub & 1) << 3);
            int kk  = ks * 16 + ((sub & 2) << 2);
            uint32_t off = (uint32_t)(row * 128 + kk * 2);
            LDSM_X4(a[mt][0], a[mt][1], a[mt][2], a[mt][3], sA + SWZ(off));
        }
#pragma unroll
        for (int np = 0; np < 4; ++np) {
            int row = wn * 64 + np * 16 + i + ((sub & 2) << 2);
            int kk  = ks * 16 + ((sub & 1) << 3);
            uint32_t off = (uint32_t)(row * 128 + kk * 2);
            uint32_t r0, r1, r2, r3;
            LDSM_X4(r0, r1, r2, r3, sB + SWZ(off));
            b[2 * np][0] = r0; b[2 * np][1] = r1;
            b[2 * np + 1][0] = r2; b[2 * np + 1][1] = r3;
        }
#pragma unroll
        for (int mt = 0; mt < 2; ++mt)
#pragma unroll
            for (int nt = 0; nt < 8; ++nt)
                MMA16816H(acc[mt][nt], a[mt], b[nt][0], b[nt][1]);
    }
}

template <int QKVMODE>
__global__ __launch_bounds__(GTHREADS, 1)
void mma_gemm_k(const __half* __restrict__ A,
                const __half* __restrict__ B,
                float* __restrict__ C,
                __half* __restrict__ Q16, __half* __restrict__ K16,
                __half* __restrict__ V16,
                int Ncols, int phiLimit) {
    extern __shared__ char sm[];
    const uint32_t s0 = smem_u32(sm);

    const int tid  = threadIdx.x;
    const int wid  = tid >> 5;
    const int lane = tid & 31;
    const int wm   = wid >> 2;
    const int wn   = wid & 3;
    const int bm   = blockIdx.y * 128;
    const int bn   = blockIdx.x * 256;
    const bool phi = bn < phiLimit;

    float acc[2][8][4];
#pragma unroll
    for (int mt = 0; mt < 2; ++mt)
#pragma unroll
        for (int nt = 0; nt < 8; ++nt)
#pragma unroll
            for (int j = 0; j < 4; ++j) acc[mt][nt][j] = 0.f;

    cpa_chunk(s0, A, B, bm, bn, 0, tid);
    CP_COMMIT();

    for (int ch = 0; ch < NCH; ++ch) {
        if (ch + 1 < NCH) {
            cpa_chunk(s0 + (uint32_t)((ch + 1) & 1) * STAGE_BYTES,
                      A, B, bm, bn, (ch + 1) * KC, tid);
            CP_COMMIT();
            CP_WAIT(1);
        } else {
            CP_WAIT(0);
        }
        __syncthreads();
        compute_chunk(s0 + (uint32_t)(ch & 1) * STAGE_BYTES, wm, wn, lane, acc);
        __syncthreads();
    }

#pragma unroll
    for (int mt = 0; mt < 2; ++mt)
#pragma unroll
        for (int nt = 0; nt < 8; ++nt) {
            int row = bm + wm * 32 + mt * 16 + (lane >> 2);
            int col = bn + wn * 64 + nt * 8 + (lane & 3) * 2;
            float2 v0 = make_float2(acc[mt][nt][0], acc[mt][nt][1]);
            float2 v1 = make_float2(acc[mt][nt][2], acc[mt][nt][3]);
            if (phi) {
                v0.x = (v0.x > 0.f) ? (v0.x + 1.f) : expf(v0.x);
                v0.y = (v0.y > 0.f) ? (v0.y + 1.f) : expf(v0.y);
                v1.x = (v1.x > 0.f) ? (v1.x + 1.f) : expf(v1.x);
                v1.y = (v1.y > 0.f) ? (v1.y + 1.f) : expf(v1.y);
            }
            if (QKVMODE == 0) {
                *(float2*)(C + (size_t)row * Ncols + col)       = v0;
                *(float2*)(C + (size_t)(row + 8) * Ncols + col) = v1;
            } else {
                const int blk  = col >> 10;
                const int lcol = col & 1023;
                __half* dst = (blk == 0) ? Q16 : (blk == 1) ? K16 : V16;
                size_t o0 = (size_t)row * DD + lcol;
                size_t o1 = (size_t)(row + 8) * DD + lcol;
                *(__half2*)(dst + o0) = __floats2half2_rn(v0.x, v0.y);
                *(__half2*)(dst + o1) = __floats2half2_rn(v1.x, v1.y);
            }
        }
}

// ---- kv_part: Kv += Kf^T V (HMMA), register-prefetch over l-chunks -------
__global__ __launch_bounds__(256)
void kv_part_k() {
    const int bh    = blockIdx.x;
    const int split = blockIdx.y;
    const int b = bh >> 4, h = bh & 15;

    __shared__ __half Kt[64 * 64];
    __shared__ __half Vt[64 * 64];
    __shared__ float k1s[DH];

    const int tid  = threadIdx.x;
    const int wid  = tid >> 5;
    const int lane = tid & 31;
    const int wm   = wid >> 1;
    const int wn   = wid & 1;
    const int i    = lane & 7;
    const int sub  = lane >> 3;
    const uint32_t sK = smem_u32(Kt);
    const uint32_t sV = smem_u32(Vt);

    if (tid < DH) k1s[tid] = 0.f;

    float acc[4][4];
#pragma unroll
    for (int nt = 0; nt < 4; ++nt)
#pragma unroll
        for (int j = 0; j < 4; ++j) acc[nt][j] = 0.f;
    float k1loc[4] = {0.f, 0.f, 0.f, 0.f};

    const int c4 = (tid & 15) << 2;
    const int lrow = tid >> 4;           // 0..15
    const size_t gbase = ((size_t)b * LL) * DD + (size_t)h * DH;
    const int l0 = split * LCHUNK;

    uint2 kr[4], vr[4];
#pragma unroll
    for (int t = 0; t < 4; ++t) {
        size_t g = gbase + (size_t)(l0 + lrow + t * 16) * DD + c4;
        kr[t] = *(const uint2*)(g_K16 + g);
        vr[t] = *(const uint2*)(g_V16 + g);
    }

    for (int ch = 0; ch < LCHUNK / 64; ++ch) {
        __syncthreads();
#pragma unroll
        for (int t = 0; t < 4; ++t) {
            int l = lrow + t * 16;
            uint32_t sw = SWZ((uint32_t)(l * 128 + c4 * 2));
            *(uint2*)((char*)Kt + sw) = kr[t];
            *(uint2*)((char*)Vt + sw) = vr[t];
            float2 f0 = __half22float2(*(__half2*)&kr[t].x);
            float2 f1 = __half22float2(*(__half2*)&kr[t].y);
            k1loc[0] += f0.x; k1loc[1] += f0.y;
            k1loc[2] += f1.x; k1loc[3] += f1.y;
        }
        __syncthreads();

        if (ch + 1 < LCHUNK / 64) {
#pragma unroll
            for (int t = 0; t < 4; ++t) {
                size_t g = gbase + (size_t)(l0 + (ch + 1) * 64 + lrow + t * 16) * DD + c4;
                kr[t] = *(const uint2*)(g_K16 + g);
                vr[t] = *(const uint2*)(g_V16 + g);
            }
        }

#pragma unroll
        for (int ks = 0; ks < 4; ++ks) {
            uint32_t a[4];
            {
                int row = ks * 16 + ((sub & 2) << 2) + i;
                int col = wm * 16 + ((sub & 1) << 3);
                uint32_t off = (uint32_t)(row * 128 + col * 2);
                LDSM_X4_T(a[0], a[1], a[2], a[3], sK + SWZ(off));
            }
            uint32_t bf[4][2];
#pragma unroll
            for (int np = 0; np < 2; ++np) {
                int row = ks * 16 + ((sub & 1) << 3) + i;
                int col = wn * 32 + np * 16 + ((sub & 2) << 2);
                uint32_t off = (uint32_t)(row * 128 + col * 2);
                uint32_t r0, r1, r2, r3;
                LDSM_X4_T(r0, r1, r2, r3, sV + SWZ(off));
                bf[2 * np][0] = r0; bf[2 * np][1] = r1;
                bf[2 * np + 1][0] = r2; bf[2 * np + 1][1] = r3;
            }
#pragma unroll
            for (int nt = 0; nt < 4; ++nt)
                MMA16816H(acc[nt], a, bf[nt][0], bf[nt][1]);
        }
    }

#pragma unroll
    for (int j = 0; j < 4; ++j) atomicAdd(&k1s[c4 + j], k1loc[j]);
    __syncthreads();

    float* kp = g_KvPart + ((size_t)bh * SPLITS + split) * (DH * DH);
    const int r0 = wm * 16 + (lane >> 2);
#pragma unroll
    for (int nt = 0; nt < 4; ++nt) {
        int cc = wn * 32 + nt * 8 + (lane & 3) * 2;
        *(float2*)(kp + r0 * DH + cc)       = make_float2(acc[nt][0], acc[nt][1]);
        *(float2*)(kp + (r0 + 8) * DH + cc) = make_float2(acc[nt][2], acc[nt][3]);
    }
    if (tid < DH)
        g_K1Part[((size_t)bh * SPLITS + split) * DH + tid] = k1s[tid];
}

// ------- reduce partials: Kv -> fp16 (grid 64x4), K1 -> fp32 --------------
__global__ __launch_bounds__(256)
void kv_reduce_k() {
    const int bh    = blockIdx.x;
    const int slice = blockIdx.y;               // 0..3, each covers 1024 elems
    const int tid   = threadIdx.x;
    const int base  = slice * 1024;
    for (int j = tid; j < 1024; j += 256) {
        int idx = base + j;
        float s = 0.f;
#pragma unroll
        for (int sp = 0; sp < SPLITS; ++sp)
            s += g_KvPart[((size_t)bh * SPLITS + sp) * (DH * DH) + idx];
        g_Kv16[(size_t)bh * (DH * DH) + idx] = __float2half_rn(s);
    }
    if (slice == 0 && tid < DH) {
        float s = 0.f;
#pragma unroll
        for (int sp = 0; sp < SPLITS; ++sp)
            s += g_K1Part[((size_t)bh * SPLITS + sp) * DH + tid];
        g_K1[bh * DH + tid] = s;
    }
}

// -------- numden: att = (Qf @ Kv16) / (Qf @ K1 + eps) via HMMA ------------
__global__ __launch_bounds__(256)
void numden_k() {
    const int bh = blockIdx.x;
    const int lt = blockIdx.y;
    const int b = bh >> 4, h = bh & 15;

    __shared__ __half Qs[64 * 64];
    __shared__ __half Kvs[64 * 64];
    __shared__ float K1s[DH];

    const int tid  = threadIdx.x;
    const int wid  = tid >> 5;
    const int lane = tid & 31;
    const int wm   = wid >> 1;
    const int wn   = wid & 1;
    const int i    = lane & 7;
    const int sub  = lane >> 3;
    const uint32_t sQ  = smem_u32(Qs);
    const uint32_t sKv = smem_u32(Kvs);

    const size_t base = ((size_t)b * LL + (size_t)lt * 64) * DD + (size_t)h * DH;
    const int c4 = (tid & 15) << 2;

#pragma unroll
    for (int t = 0; t < 4; ++t) {
        int r = (tid >> 4) + t * 16;
        uint32_t off = (uint32_t)(r * 128 + c4 * 2);
        uint32_t sw  = SWZ(off);
        *(uint2*)((char*)Qs + sw) =
            *(const uint2*)(g_Q16 + base + (size_t)r * DD + c4);
        *(uint2*)((char*)Kvs + sw) =
            *(const uint2*)(g_Kv16 + (size_t)bh * DH * DH + r * DH + c4);
    }
    if (tid < DH) K1s[tid] = g_K1[bh * DH + tid];
    __syncthreads();

    float acc[4][4];
#pragma unroll
    for (int nt = 0; nt < 4; ++nt)
#pragma unroll
        for (int j = 0; j < 4; ++j) acc[nt][j] = 0.f;
    float den_lo = 0.f, den_hi = 0.f;
    const int q2 = (lane & 3) * 2;

#pragma unroll
    for (int ks = 0; ks < 4; ++ks) {
        uint32_t a[4];
        {
            int row = wm * 16 + i + ((sub & 1) << 3);
            int kk  = ks * 16 + ((sub & 2) << 2);
            uint32_t off = (uint32_t)(row * 128 + kk * 2);
            LDSM_X4(a[0], a[1], a[2], a[3], sQ + SWZ(off));
        }
        float k00 = K1s[ks * 16 + q2],     k01 = K1s[ks * 16 + q2 + 1];
        float k10 = K1s[ks * 16 + 8 + q2], k11 = K1s[ks * 16 + 8 + q2 + 1];
        float2 f;
        f = __half22float2(*(__half2*)&a[0]); den_lo += f.x * k00 + f.y * k01;
        f = __half22float2(*(__half2*)&a[1]); den_hi += f.x * k00 + f.y * k01;
        f = __half22float2(*(__half2*)&a[2]); den_lo += f.x * k10 + f.y * k11;
        f = __half22float2(*(__half2*)&a[3]); den_hi += f.x * k10 + f.y * k11;

        uint32_t bf[4][2];
#pragma unroll
        for (int np = 0; np < 2; ++np) {
            int row = ks * 16 + ((sub & 1) << 3) + i;
            int col = wn * 32 + np * 16 + ((sub & 2) << 2);
            uint32_t off = (uint32_t)(row * 128 + col * 2);
            uint32_t r0, r1, r2, r3;
            LDSM_X4_T(r0, r1, r2, r3, sKv + SWZ(off));
            bf[2 * np][0] = r0; bf[2 * np][1] = r1;
            bf[2 * np + 1][0] = r2; bf[2 * np + 1][1] = r3;
        }
#pragma unroll
        for (int nt = 0; nt < 4; ++nt)
            MMA16816H(acc[nt], a, bf[nt][0], bf[nt][1]);
    }

#pragma unroll
    for (int s = 1; s < 4; s <<= 1) {
        den_lo += __shfl_xor_sync(0xffffffffu, den_lo, s);
        den_hi += __shfl_xor_sync(0xffffffffu, den_hi, s);
    }
    const float inv_lo = 1.f / (den_lo + EPSV);
    const float inv_hi = 1.f / (den_hi + EPSV);

    const int r0 = wm * 16 + (lane >> 2);
#pragma unroll
    for (int nt = 0; nt < 4; ++nt) {
        int cc = wn * 32 + nt * 8 + (lane & 3) * 2;
        __half2 o0 = __floats2half2_rn(acc[nt][0] * inv_lo, acc[nt][1] * inv_lo);
        __half2 o1 = __floats2half2_rn(acc[nt][2] * inv_hi, acc[nt][3] * inv_hi);
        *(uint32_t*)(g_att16 + base + (size_t)r0 * DD + cc)       = *(uint32_t*)&o0;
        *(uint32_t*)(g_att16 + base + (size_t)(r0 + 8) * DD + cc) = *(uint32_t*)&o1;
    }
}

// --------------------------- host launch --------------------------------
extern "C" void kernel_launch(void* const* d_in, const int* in_sizes, int n_in,
                              void* d_out, int out_size) {
    const float* x  = (const float*)d_in[0];
    const float* Wq = (const float*)d_in[1];
    const float* Wk = (const float*)d_in[2];
    const float* Wv = (const float*)d_in[3];
    const float* Wo = (const float*)d_in[4];
    float* out = (float*)d_out;

    __half *x16, *q16, *k16, *v16, *att16, *wt;
    cudaGetSymbolAddress((void**)&x16,   g_X16);
    cudaGetSymbolAddress((void**)&q16,   g_Q16);
    cudaGetSymbolAddress((void**)&k16,   g_K16);
    cudaGetSymbolAddress((void**)&v16,   g_V16);
    cudaGetSymbolAddress((void**)&att16, g_att16);
    cudaGetSymbolAddress((void**)&wt,    g_Wt);

    cudaFuncSetAttribute(mma_gemm_k<0>,
                         cudaFuncAttributeMaxDynamicSharedMemorySize, GEMM_SMEM);
    cudaFuncSetAttribute(mma_gemm_k<1>,
                         cudaFuncAttributeMaxDynamicSharedMemorySize, GEMM_SMEM);

    // fused pre-pass: x conversion + 4 weight transposes in one launch
    prepass_k<<<XBLOCKS + 4096, 256>>>(x, x16, Wq, Wk, Wv, Wo, wt);

    // fused QKV GEMM: N = 3072, phi on cols < 2048; writes Q16/K16/V16
    dim3 gqkv(NQKV / 256, MLROWS / 128);      // (12, 256)
    mma_gemm_k<1><<<gqkv, GTHREADS, GEMM_SMEM>>>(
        x16, wt, nullptr, q16, k16, v16, NQKV, 2 * DD);

    kv_part_k<<<dim3(BB * HH, SPLITS), 256>>>();
    kv_reduce_k<<<dim3(BB * HH, 4), 256>>>();
    numden_k<<<dim3(BB * HH, LL / 64), 256>>>();

    // output GEMM: N = 1024, no phi, fp32 out
    dim3 gout(DD / 256, MLROWS / 128);        // (4, 256)
    mma_gemm_k<0><<<gout, GTHREADS, GEMM_SMEM>>>(
        att16, wt + 3 * (size_t)DD * DD, out,
        nullptr, nullptr, nullptr, DD, 0);
}

// round 16
// speedup vs baseline: 1.0348x; 1.0063x over previous
#include <cuda_runtime.h>
#include <cuda_fp16.h>
#include <stdint.h>
#include <math.h>

#define BB     4
#define LL     8192
#define DD     1024
#define HH     16
#define DH     64
#define MLROWS (BB * LL)          // 32768
#define NQKV   (3 * DD)           // 3072
#define EPSV   1e-6f
#define SPLITS 16
#define LCHUNK (LL / SPLITS)      // 512

// GEMM tiling: CTA 128x256, 16 warps (4x4), warp tile 32x64, K-chunk 64
#define KC 64
#define NCH (DD / KC)              // 16
#define GTHREADS 512
#define STAGE_BYTES 49152          // A 16K, B 32K
#define GEMM_SMEM   (2 * STAGE_BYTES)

// ---------------- scratch (static device globals; no allocation) ----------
__device__ __half g_X16[(size_t)MLROWS * DD];
__device__ __half g_Q16[(size_t)MLROWS * DD];   // phi(xWq)
__device__ __half g_K16[(size_t)MLROWS * DD];   // phi(xWk)
__device__ __half g_V16[(size_t)MLROWS * DD];   // xWv
__device__ __half g_att16[(size_t)MLROWS * DD];
__device__ float g_KvPart[BB * HH * SPLITS * DH * DH];
__device__ float g_K1Part[BB * HH * SPLITS * DH];
__device__ __half g_Kv16[BB * HH * DH * DH];
__device__ float g_K1[BB * HH * DH];
__device__ __half g_Wt[4][DD * DD];             // [N,K] fp16 (Wq|Wk|Wv|Wo)

// =========================== helpers ==================================
__device__ __forceinline__ uint32_t smem_u32(const void* p) {
    return (uint32_t)__cvta_generic_to_shared(p);
}

#define LDSM_X4(r0, r1, r2, r3, addr) \
    asm volatile("ldmatrix.sync.aligned.m8n8.x4.shared.b16 {%0,%1,%2,%3}, [%4];" \
                 : "=r"(r0), "=r"(r1), "=r"(r2), "=r"(r3) : "r"(addr))

#define LDSM_X4_T(r0, r1, r2, r3, addr) \
    asm volatile("ldmatrix.sync.aligned.m8n8.x4.trans.shared.b16 {%0,%1,%2,%3}, [%4];" \
                 : "=r"(r0), "=r"(r1), "=r"(r2), "=r"(r3) : "r"(addr))

#define MMA16816H(d, a, b0, b1) \
    asm volatile("mma.sync.aligned.m16n8k16.row.col.f32.f16.f16.f32 " \
                 "{%0,%1,%2,%3}, {%4,%5,%6,%7}, {%8,%9}, {%0,%1,%2,%3};" \
                 : "+f"((d)[0]), "+f"((d)[1]), "+f"((d)[2]), "+f"((d)[3]) \
                 : "r"((a)[0]), "r"((a)[1]), "r"((a)[2]), "r"((a)[3]), \
                   "r"(b0), "r"(b1))

__device__ __forceinline__ void cp16(uint32_t dst, const void* src) {
    asm volatile("cp.async.cg.shared.global [%0], [%1], 16;"
                 :: "r"(dst), "l"(src));
}
#define CP_COMMIT() asm volatile("cp.async.commit_group;" ::: "memory")
#define CP_WAIT(n)  asm volatile("cp.async.wait_group %0;" :: "n"(n) : "memory")

#define SWZ(off) ((off) ^ (((off) >> 3) & 0x70))

// ====== fused pre-pass: x fp32->fp16 AND four W[K,N]->Wt[N,K] fp16 ========
#define XBLOCKS (MLROWS * DD / 1024)            // 32768
__global__ __launch_bounds__(256)
void prepass_k(const float* __restrict__ X, __half* __restrict__ H,
               const float* __restrict__ W0, const float* __restrict__ W1,
               const float* __restrict__ W2, const float* __restrict__ W3,
               __half* __restrict__ T) {
    if (blockIdx.x < XBLOCKS) {
        size_t i = ((size_t)blockIdx.x * 256 + threadIdx.x) * 4;
        float4 v = *(const float4*)(X + i);
        __half2 a = __floats2half2_rn(v.x, v.y);
        __half2 b = __floats2half2_rn(v.z, v.w);
        *(uint2*)(H + i) = make_uint2(*(uint32_t*)&a, *(uint32_t*)&b);
        return;
    }
    const int idx = blockIdx.x - XBLOCKS;       // 0..4095
    const int z   = idx >> 10;                  // 0..3
    const int rem = idx & 1023;
    const float* W = (z == 0) ? W0 : (z == 1) ? W1 : (z == 2) ? W2 : W3;
    __half* Tz = T + (size_t)z * DD * DD;
    __shared__ float t[32][33];
    const int nb = (rem & 31) * 32;
    const int kb = (rem >> 5) * 32;
    const int tx = threadIdx.x & 31;
    const int ty = threadIdx.x >> 5;
    for (int i = ty; i < 32; i += 8)
        t[i][tx] = W[(size_t)(kb + i) * DD + nb + tx];
    __syncthreads();
    for (int i = ty; i < 32; i += 8) {
        size_t o = (size_t)(nb + i) * DD + kb + tx;
        Tz[o] = __float2half_rn(t[tx][i]);
    }
}

// ========== mma.sync fp16 GEMM (1-term, 2-stage cp.async) =================
__device__ __forceinline__ void cpa_chunk(
    uint32_t sb,
    const __half* __restrict__ A, const __half* __restrict__ B,
    int bm, int bn, int k0, int tid) {
#pragma unroll
    for (int t = 0; t < 2; ++t) {
        int idx = tid + t * GTHREADS;
        int row = idx >> 3;
        int cb  = (idx & 7) << 4;
        uint32_t off = (uint32_t)(row * 128 + cb);
        cp16(sb + SWZ(off), (const char*)(A + (size_t)(bm + row) * DD + k0) + cb);
    }
#pragma unroll
    for (int t = 0; t < 4; ++t) {
        int idx = tid + t * GTHREADS;
        int row = idx >> 3;
        int cb  = (idx & 7) << 4;
        uint32_t off = (uint32_t)(row * 128 + cb);
        cp16(sb + 16384 + SWZ(off), (const char*)(B + (size_t)(bn + row) * DD + k0) + cb);
    }
}

__device__ __forceinline__ void compute_chunk(
    uint32_t sb, int wm, int wn, int lane, float acc[2][8][4]) {
    const uint32_t sA = sb, sB = sb + 16384;
    const int i   = lane & 7;
    const int sub = lane >> 3;
#pragma unroll
    for (int ks = 0; ks < 4; ++ks) {
        uint32_t a[2][4], b[8][2];
#pragma unroll
        for (int mt = 0; mt < 2; ++mt) {
            int row = wm * 32 + mt * 16 + i + ((sub & 1) << 3);
            int kk  = ks * 16 + ((sub & 2) << 2);
            uint32_t off = (uint32_t)(row * 128 + kk * 2);
            LDSM_X4(a[mt][0], a[mt][1], a[mt][2], a[mt][3], sA + SWZ(off));
        }
#pragma unroll
        for (int np = 0; np < 4; ++np) {
            int row = wn * 64 + np * 16 + i + ((sub & 2) << 2);
            int kk  = ks * 16 + ((sub & 1) << 3);
            uint32_t off = (uint32_t)(row * 128 + kk * 2);
            uint32_t r0, r1, r2, r3;
            LDSM_X4(r0, r1, r2, r3, sB + SWZ(off));
            b[2 * np][0] = r0; b[2 * np][1] = r1;
            b[2 * np + 1][0] = r2; b[2 * np + 1][1] = r3;
        }
#pragma unroll
        for (int mt = 0; mt < 2; ++mt)
#pragma unroll
            for (int nt = 0; nt < 8; ++nt)
                MMA16816H(acc[mt][nt], a[mt], b[nt][0], b[nt][1]);
    }
}

template <int QKVMODE>
__global__ __launch_bounds__(GTHREADS, 1)
void mma_gemm_k(const __half* __restrict__ A,
                const __half* __restrict__ B,
                float* __restrict__ C,
                __half* __restrict__ Q16, __half* __restrict__ K16,
                __half* __restrict__ V16,
                int Ncols, int phiLimit) {
    extern __shared__ char sm[];
    const uint32_t s0 = smem_u32(sm);

    const int tid  = threadIdx.x;
    const int wid  = tid >> 5;
    const int lane = tid & 31;
    const int wm   = wid >> 2;
    const int wn   = wid & 3;
    const int bm   = blockIdx.y * 128;
    const int bn   = blockIdx.x * 256;
    const bool phi = bn < phiLimit;

    float acc[2][8][4];
#pragma unroll
    for (int mt = 0; mt < 2; ++mt)
#pragma unroll
        for (int nt = 0; nt < 8; ++nt)
#pragma unroll
            for (int j = 0; j < 4; ++j) acc[mt][nt][j] = 0.f;

    cpa_chunk(s0, A, B, bm, bn, 0, tid);
    CP_COMMIT();

    for (int ch = 0; ch < NCH; ++ch) {
        if (ch + 1 < NCH) {
            cpa_chunk(s0 + (uint32_t)((ch + 1) & 1) * STAGE_BYTES,
                      A, B, bm, bn, (ch + 1) * KC, tid);
            CP_COMMIT();
            CP_WAIT(1);
        } else {
            CP_WAIT(0);
        }
        __syncthreads();
        compute_chunk(s0 + (uint32_t)(ch & 1) * STAGE_BYTES, wm, wn, lane, acc);
        __syncthreads();
    }

#pragma unroll
    for (int mt = 0; mt < 2; ++mt)
#pragma unroll
        for (int nt = 0; nt < 8; ++nt) {
            int row = bm + wm * 32 + mt * 16 + (lane >> 2);
            int col = bn + wn * 64 + nt * 8 + (lane & 3) * 2;
            float2 v0 = make_float2(acc[mt][nt][0], acc[mt][nt][1]);
            float2 v1 = make_float2(acc[mt][nt][2], acc[mt][nt][3]);
            if (phi) {
                v0.x = (v0.x > 0.f) ? (v0.x + 1.f) : expf(v0.x);
                v0.y = (v0.y > 0.f) ? (v0.y + 1.f) : expf(v0.y);
                v1.x = (v1.x > 0.f) ? (v1.x + 1.f) : expf(v1.x);
                v1.y = (v1.y > 0.f) ? (v1.y + 1.f) : expf(v1.y);
            }
            if (QKVMODE == 0) {
                *(float2*)(C + (size_t)row * Ncols + col)       = v0;
                *(float2*)(C + (size_t)(row + 8) * Ncols + col) = v1;
            } else {
                const int blk  = col >> 10;
                const int lcol = col & 1023;
                __half* dst = (blk == 0) ? Q16 : (blk == 1) ? K16 : V16;
                size_t o0 = (size_t)row * DD + lcol;
                size_t o1 = (size_t)(row + 8) * DD + lcol;
                *(__half2*)(dst + o0) = __floats2half2_rn(v0.x, v0.y);
                *(__half2*)(dst + o1) = __floats2half2_rn(v1.x, v1.y);
            }
        }
}

// ---- kv_part: Kv += Kf^T V (HMMA), double-buffered smem, 1 sync/chunk ----
__global__ __launch_bounds__(256)
void kv_part_k() {
    const int bh    = blockIdx.x;
    const int split = blockIdx.y;
    const int b = bh >> 4, h = bh & 15;

    __shared__ __half Kt[2][64 * 64];
    __shared__ __half Vt[2][64 * 64];
    __shared__ float k1s[DH];

    const int tid  = threadIdx.x;
    const int wid  = tid >> 5;
    const int lane = tid & 31;
    const int wm   = wid >> 1;
    const int wn   = wid & 1;
    const int i    = lane & 7;
    const int sub  = lane >> 3;

    if (tid < DH) k1s[tid] = 0.f;

    float acc[4][4];
#pragma unroll
    for (int nt = 0; nt < 4; ++nt)
#pragma unroll
        for (int j = 0; j < 4; ++j) acc[nt][j] = 0.f;
    float k1loc[4] = {0.f, 0.f, 0.f, 0.f};

    const int c4 = (tid & 15) << 2;
    const int lrow = tid >> 4;           // 0..15
    const size_t gbase = ((size_t)b * LL) * DD + (size_t)h * DH;
    const int l0 = split * LCHUNK;
    const int NCHK = LCHUNK / 64;        // 8

    uint2 kr[4], vr[4];
    // preload chunk 0 and store into stage 0 (no readers yet)
#pragma unroll
    for (int t = 0; t < 4; ++t) {
        size_t g = gbase + (size_t)(l0 + lrow + t * 16) * DD + c4;
        kr[t] = *(const uint2*)(g_K16 + g);
        vr[t] = *(const uint2*)(g_V16 + g);
    }
#pragma unroll
    for (int t = 0; t < 4; ++t) {
        int l = lrow + t * 16;
        uint32_t sw = SWZ((uint32_t)(l * 128 + c4 * 2));
        *(uint2*)((char*)Kt[0] + sw) = kr[t];
        *(uint2*)((char*)Vt[0] + sw) = vr[t];
        float2 f0 = __half22float2(*(__half2*)&kr[t].x);
        float2 f1 = __half22float2(*(__half2*)&kr[t].y);
        k1loc[0] += f0.x; k1loc[1] += f0.y;
        k1loc[2] += f1.x; k1loc[3] += f1.y;
    }

    for (int ch = 0; ch < NCHK; ++ch) {
        if (ch + 1 < NCHK) {             // issue next chunk's LDGs early
#pragma unroll
            for (int t = 0; t < 4; ++t) {
                size_t g = gbase + (size_t)(l0 + (ch + 1) * 64 + lrow + t * 16) * DD + c4;
                kr[t] = *(const uint2*)(g_K16 + g);
                vr[t] = *(const uint2*)(g_V16 + g);
            }
        }
        __syncthreads();                 // stage ch visible; stage (ch+1)&1 free

        const uint32_t sK = smem_u32(Kt[ch & 1]);
        const uint32_t sV = smem_u32(Vt[ch & 1]);
#pragma unroll
        for (int ks = 0; ks < 4; ++ks) {
            uint32_t a[4];
            {
                int row = ks * 16 + ((sub & 2) << 2) + i;
                int col = wm * 16 + ((sub & 1) << 3);
                uint32_t off = (uint32_t)(row * 128 + col * 2);
                LDSM_X4_T(a[0], a[1], a[2], a[3], sK + SWZ(off));
            }
            uint32_t bf[4][2];
#pragma unroll
            for (int np = 0; np < 2; ++np) {
                int row = ks * 16 + ((sub & 1) << 3) + i;
                int col = wn * 32 + np * 16 + ((sub & 2) << 2);
                uint32_t off = (uint32_t)(row * 128 + col * 2);
                uint32_t r0, r1, r2, r3;
                LDSM_X4_T(r0, r1, r2, r3, sV + SWZ(off));
                bf[2 * np][0] = r0; bf[2 * np][1] = r1;
                bf[2 * np + 1][0] = r2; bf[2 * np + 1][1] = r3;
            }
#pragma unroll
            for (int nt = 0; nt < 4; ++nt)
                MMA16816H(acc[nt], a, bf[nt][0], bf[nt][1]);
        }

        if (ch + 1 < NCHK) {             // store next chunk into other stage
#pragma unroll
            for (int t = 0; t < 4; ++t) {
                int l = lrow + t * 16;
                uint32_t sw = SWZ((uint32_t)(l * 128 + c4 * 2));
                *(uint2*)((char*)Kt[(ch + 1) & 1] + sw) = kr[t];
                *(uint2*)((char*)Vt[(ch + 1) & 1] + sw) = vr[t];
                float2 f0 = __half22float2(*(__half2*)&kr[t].x);
                float2 f1 = __half22float2(*(__half2*)&kr[t].y);
                k1loc[0] += f0.x; k1loc[1] += f0.y;
                k1loc[2] += f1.x; k1loc[3] += f1.y;
            }
        }
    }

#pragma unroll
    for (int j = 0; j < 4; ++j) atomicAdd(&k1s[c4 + j], k1loc[j]);
    __syncthreads();

    float* kp = g_KvPart + ((size_t)bh * SPLITS + split) * (DH * DH);
    const int r0 = wm * 16 + (lane >> 2);
#pragma unroll
    for (int nt = 0; nt < 4; ++nt) {
        int cc = wn * 32 + nt * 8 + (lane & 3) * 2;
        *(float2*)(kp + r0 * DH + cc)       = make_float2(acc[nt][0], acc[nt][1]);
        *(float2*)(kp + (r0 + 8) * DH + cc) = make_float2(acc[nt][2], acc[nt][3]);
    }
    if (tid < DH)
        g_K1Part[((size_t)bh * SPLITS + split) * DH + tid] = k1s[tid];
}

// ------- reduce partials: Kv -> fp16 (grid 64x4), K1 -> fp32 --------------
__global__ __launch_bounds__(256)
void kv_reduce_k() {
    const int bh    = blockIdx.x;
    const int slice = blockIdx.y;               // 0..3, each covers 1024 elems
    const int tid   = threadIdx.x;
    const int base  = slice * 1024;
    for (int j = tid; j < 1024; j += 256) {
        int idx = base + j;
        float s = 0.f;
#pragma unroll
        for (int sp = 0; sp < SPLITS; ++sp)
            s += g_KvPart[((size_t)bh * SPLITS + sp) * (DH * DH) + idx];
        g_Kv16[(size_t)bh * (DH * DH) + idx] = __float2half_rn(s);
    }
    if (slice == 0 && tid < DH) {
        float s = 0.f;
#pragma unroll
        for (int sp = 0; sp < SPLITS; ++sp)
            s += g_K1Part[((size_t)bh * SPLITS + sp) * DH + tid];
        g_K1[bh * DH + tid] = s;
    }
}

// -------- numden: att = (Qf @ Kv16) / (Qf @ K1 + eps) via HMMA ------------
__global__ __launch_bounds__(256)
void numden_k() {
    const int bh = blockIdx.x;
    const int lt = blockIdx.y;
    const int b = bh >> 4, h = bh & 15;

    __shared__ __half Qs[64 * 64];
    __shared__ __half Kvs[64 * 64];
    __shared__ float K1s[DH];

    const int tid  = threadIdx.x;
    const int wid  = tid >> 5;
    const int lane = tid & 31;
    const int wm   = wid >> 1;
    const int wn   = wid & 1;
    const int i    = lane & 7;
    const int sub  = lane >> 3;
    const uint32_t sQ  = smem_u32(Qs);
    const uint32_t sKv = smem_u32(Kvs);

    const size_t base = ((size_t)b * LL + (size_t)lt * 64) * DD + (size_t)h * DH;
    const int c4 = (tid & 15) << 2;

#pragma unroll
    for (int t = 0; t < 4; ++t) {
        int r = (tid >> 4) + t * 16;
        uint32_t off = (uint32_t)(r * 128 + c4 * 2);
        uint32_t sw  = SWZ(off);
        *(uint2*)((char*)Qs + sw) =
            *(const uint2*)(g_Q16 + base + (size_t)r * DD + c4);
        *(uint2*)((char*)Kvs + sw) =
            *(const uint2*)(g_Kv16 + (size_t)bh * DH * DH + r * DH + c4);
    }
    if (tid < DH) K1s[tid] = g_K1[bh * DH + tid];
    __syncthreads();

    float acc[4][4];
#pragma unroll
    for (int nt = 0; nt < 4; ++nt)
#pragma unroll
        for (int j = 0; j < 4; ++j) acc[nt][j] = 0.f;
    float den_lo = 0.f, den_hi = 0.f;
    const int q2 = (lane & 3) * 2;

#pragma unroll
    for (int ks = 0; ks < 4; ++ks) {
        uint32_t a[4];
        {
            int row = wm * 16 + i + ((sub & 1) << 3);
            int kk  = ks * 16 + ((sub & 2) << 2);
            uint32_t off = (uint32_t)(row * 128 + kk * 2);
            LDSM_X4(a[0], a[1], a[2], a[3], sQ + SWZ(off));
        }
        float k00 = K1s[ks * 16 + q2],     k01 = K1s[ks * 16 + q2 + 1];
        float k10 = K1s[ks * 16 + 8 + q2], k11 = K1s[ks * 16 + 8 + q2 + 1];
        float2 f;
        f = __half22float2(*(__half2*)&a[0]); den_lo += f.x * k00 + f.y * k01;
        f = __half22float2(*(__half2*)&a[1]); den_hi += f.x * k00 + f.y * k01;
        f = __half22float2(*(__half2*)&a[2]); den_lo += f.x * k10 + f.y * k11;
        f = __half22float2(*(__half2*)&a[3]); den_hi += f.x * k10 + f.y * k11;

        uint32_t bf[4][2];
#pragma unroll
        for (int np = 0; np < 2; ++np) {
            int row = ks * 16 + ((sub & 1) << 3) + i;
            int col = wn * 32 + np * 16 + ((sub & 2) << 2);
            uint32_t off = (uint32_t)(row * 128 + col * 2);
            uint32_t r0, r1, r2, r3;
            LDSM_X4_T(r0, r1, r2, r3, sKv + SWZ(off));
            bf[2 * np][0] = r0; bf[2 * np][1] = r1;
            bf[2 * np + 1][0] = r2; bf[2 * np + 1][1] = r3;
        }
#pragma unroll
        for (int nt = 0; nt < 4; ++nt)
            MMA16816H(acc[nt], a, bf[nt][0], bf[nt][1]);
    }

#pragma unroll
    for (int s = 1; s < 4; s <<= 1) {
        den_lo += __shfl_xor_sync(0xffffffffu, den_lo, s);
        den_hi += __shfl_xor_sync(0xffffffffu, den_hi, s);
    }
    const float inv_lo = 1.f / (den_lo + EPSV);
    const float inv_hi = 1.f / (den_hi + EPSV);

    const int r0 = wm * 16 + (lane >> 2);
#pragma unroll
    for (int nt = 0; nt < 4; ++nt) {
        int cc = wn * 32 + nt * 8 + (lane & 3) * 2;
        __half2 o0 = __floats2half2_rn(acc[nt][0] * inv_lo, acc[nt][1] * inv_lo);
        __half2 o1 = __floats2half2_rn(acc[nt][2] * inv_hi, acc[nt][3] * inv_hi);
        *(uint32_t*)(g_att16 + base + (size_t)r0 * DD + cc)       = *(uint32_t*)&o0;
        *(uint32_t*)(g_att16 + base + (size_t)(r0 + 8) * DD + cc) = *(uint32_t*)&o1;
    }
}

// --------------------------- host launch --------------------------------
extern "C" void kernel_launch(void* const* d_in, const int* in_sizes, int n_in,
                              void* d_out, int out_size) {
    const float* x  = (const float*)d_in[0];
    const float* Wq = (const float*)d_in[1];
    const float* Wk = (const float*)d_in[2];
    const float* Wv = (const float*)d_in[3];
    const float* Wo = (const float*)d_in[4];
    float* out = (float*)d_out;

    __half *x16, *q16, *k16, *v16, *att16, *wt;
    cudaGetSymbolAddress((void**)&x16,   g_X16);
    cudaGetSymbolAddress((void**)&q16,   g_Q16);
    cudaGetSymbolAddress((void**)&k16,   g_K16);
    cudaGetSymbolAddress((void**)&v16,   g_V16);
    cudaGetSymbolAddress((void**)&att16, g_att16);
    cudaGetSymbolAddress((void**)&wt,    g_Wt);

    cudaFuncSetAttribute(mma_gemm_k<0>,
                         cudaFuncAttributeMaxDynamicSharedMemorySize, GEMM_SMEM);
    cudaFuncSetAttribute(mma_gemm_k<1>,
                         cudaFuncAttributeMaxDynamicSharedMemorySize, GEMM_SMEM);

    // fused pre-pass: x conversion + 4 weight transposes in one launch
    prepass_k<<<XBLOCKS + 4096, 256>>>(x, x16, Wq, Wk, Wv, Wo, wt);

    // fused QKV GEMM: N = 3072, phi on cols < 2048; writes Q16/K16/V16
    dim3 gqkv(NQKV / 256, MLROWS / 128);      // (12, 256)
    mma_gemm_k<1><<<gqkv, GTHREADS, GEMM_SMEM>>>(
        x16, wt, nullptr, q16, k16, v16, NQKV, 2 * DD);

    kv_part_k<<<dim3(BB * HH, SPLITS), 256>>>();
    kv_reduce_k<<<dim3(BB * HH, 4), 256>>>();
    numden_k<<<dim3(BB * HH, LL / 64), 256>>>();

    // output GEMM: N = 1024, no phi, fp32 out
    dim3 gout(DD / 256, MLROWS / 128);        // (4, 256)
    mma_gemm_k<0><<<gout, GTHREADS, GEMM_SMEM>>>(
        att16, wt + 3 * (size_t)DD * DD, out,
        nullptr, nullptr, nullptr, DD, 0);
}